// round 7
// baseline (speedup 1.0000x reference)
#include <cuda_runtime.h>
#include <cuda_fp16.h>
#include <cstdint>

// ---------------------------------------------------------------------------
// Poly2d via warp-level HMMA (mma.sync m16n8k16, fp16 in / fp32 acc).
// 54 features/channel (9 linear + 45 symmetric pairs) padded to 64; const
// term folded into bias. Round 7: 512 threads / 16 warps per CTA (4x4 warp
// grid, 32x16 warp tile) to double warps/SMSP; featgen split in quarters.
// ---------------------------------------------------------------------------

#define NCH   64
#define NOUT  64
#define KPAD  64

__device__ __align__(16) unsigned short g_W16[NCH * NOUT * KPAD];
__device__ float g_bias2[NOUT];

// dynamic smem layout (bytes)
#define OFF_A   0                         // 2 buf x (2 ch x 16384) = 65536
#define OFF_B   65536                     // 2 buf x (2 ch x 8192)  = 32768
#define OFF_X   (OFF_B + 32768)           // 2 buf x 2 ch x 272 floats = 4352
#define SMEM_SZ (OFF_X + 4352)

__device__ __forceinline__ uint32_t s2u(const void* p) {
    return (uint32_t)__cvta_generic_to_shared(p);
}
__device__ __forceinline__ void cpa4(uint32_t s, const void* g, bool ok) {
    asm volatile("cp.async.ca.shared.global [%0], [%1], 4, %2;\n"
                 :: "r"(s), "l"(g), "r"(ok ? 4 : 0));
}
__device__ __forceinline__ void cpa16(uint32_t s, const void* g) {
    asm volatile("cp.async.cg.shared.global [%0], [%1], 16;\n"
                 :: "r"(s), "l"(g));
}
__device__ __forceinline__ uint32_t swz(uint32_t off) {   // SW128
    return off ^ ((off >> 3) & 0x70);
}
__device__ __forceinline__ void ldsm4(uint32_t& r0, uint32_t& r1, uint32_t& r2,
                                      uint32_t& r3, uint32_t addr) {
    asm volatile("ldmatrix.sync.aligned.m8n8.x4.shared.b16 {%0,%1,%2,%3}, [%4];"
                 : "=r"(r0), "=r"(r1), "=r"(r2), "=r"(r3) : "r"(addr));
}
__device__ __forceinline__ void mma16816(float& c0, float& c1, float& c2, float& c3,
                                         uint32_t a0, uint32_t a1, uint32_t a2,
                                         uint32_t a3, uint32_t b0, uint32_t b1) {
    asm volatile(
        "mma.sync.aligned.m16n8k16.row.col.f32.f16.f16.f32 "
        "{%0,%1,%2,%3}, {%4,%5,%6,%7}, {%8,%9}, {%0,%1,%2,%3};"
        : "+f"(c0), "+f"(c1), "+f"(c2), "+f"(c3)
        : "r"(a0), "r"(a1), "r"(a2), "r"(a3), "r"(b0), "r"(b1));
}

// quarter Q computes features [16Q, 16Q+16) — all ranges static post-unroll
template <int Q>
__device__ __forceinline__ void gen_quarter(const float* t, float* fl) {
    int k = 0;
    #pragma unroll
    for (int tt = 0; tt < 9; ++tt) {
        if (k >= Q * 16 && k < Q * 16 + 16) fl[k - Q * 16] = t[tt];
        ++k;
    }
    #pragma unroll
    for (int i = 0; i < 9; ++i)
        #pragma unroll
        for (int j = i; j < 9; ++j) {
            if (k >= Q * 16 && k < Q * 16 + 16) fl[k - Q * 16] = t[i] * t[j];
            ++k;
        }
    #pragma unroll
    for (; k < 64; ++k)
        if (k >= Q * 16 && k < Q * 16 + 16) fl[k - Q * 16] = 0.0f;
}

// ---------------------------------------------------------------------------
// Prep: pack symmetric weights -> fp16, SW128 pre-applied; fold const term
// into bias. block = channel (64), thread = output o (64).
// ---------------------------------------------------------------------------
__global__ void poly_prep(const float* __restrict__ filters,
                          const float* __restrict__ biases) {
    __shared__ __align__(16) unsigned short wsm[NOUT * KPAD];
    const int c = blockIdx.x, o = threadIdx.x;
    const float* F = filters + o * 6400 + c * 100;

    float v[KPAD];
    int k = 0;
    #pragma unroll
    for (int t = 1; t <= 9; ++t) v[k++] = F[t] + F[t * 10];
    #pragma unroll
    for (int i = 1; i <= 9; ++i)
        #pragma unroll
        for (int j = i; j <= 9; ++j)
            v[k++] = (i == j) ? F[i * 10 + i] : (F[i * 10 + j] + F[j * 10 + i]);
    #pragma unroll
    for (; k < KPAD; ++k) v[k] = 0.0f;

    #pragma unroll
    for (int kk = 0; kk < KPAD; ++kk)
        wsm[swz((uint32_t)(o * 128 + kk * 2)) >> 1] =
            __half_as_ushort(__float2half_rn(v[kk]));
    __syncthreads();
    uint4* dst = (uint4*)(g_W16 + c * NOUT * KPAD);
    const uint4* srcp = (const uint4*)wsm;
    for (int i = o; i < 512; i += 64) dst[i] = srcp[i];

    if (c == 0) {
        float s = biases[o];
        for (int cc = 0; cc < NCH; ++cc) s += filters[o * 6400 + cc * 100];
        g_bias2[o] = s;
    }
}

// ---------------------------------------------------------------------------
// Main kernel: 128 CTAs (b, row-pair) x 512 threads (16 warps).
// Warp grid 4x4 over D[128 px, 64 o], warp tile 32x16.
// Feature gen: thread = pixel (tid&127) x quarter (tid>>7).
// ---------------------------------------------------------------------------
extern __shared__ unsigned char smdyn[];

__global__ void __launch_bounds__(512, 1)
poly_mma(const float* __restrict__ x, float* __restrict__ out) {
    const uint32_t smb = s2u(smdyn);
    const int tid = threadIdx.x, lane = tid & 31, wid = tid >> 5;
    const int m = tid & 127, h = tid >> 7;          // pixel, feature-quarter
    const int ry = m >> 6, wcol = m & 63;
    const int mrow = wid >> 2, ncol = wid & 3;      // 4x4 warp grid
    const int b = blockIdx.x >> 5;
    const int r0 = (blockIdx.x & 31) * 2;

    float acc[2][2][4];                             // [mt][n8][q]
    #pragma unroll
    for (int mt = 0; mt < 2; ++mt)
        #pragma unroll
        for (int n8 = 0; n8 < 2; ++n8)
            #pragma unroll
            for (int q = 0; q < 4; ++q) acc[mt][n8][q] = 0.0f;

    // stage channel pair (2j, 2j+1) into buffer j&1
    auto stage = [&](int j) {
        const uint32_t buf = (uint32_t)(j & 1);
        #pragma unroll
        for (int i = tid; i < 544; i += 512) {      // 2 ch x 4 rows x 68 cols
            const int p = i / 272, rem = i % 272;
            const int rr = rem / 68, col = rem % 68;
            const int gr = r0 - 1 + rr, gw = col - 1;
            const bool ok = ((unsigned)gr < 64u) && ((unsigned)gw < 64u);
            const int c = 2 * j + p;
            const float* src =
                x + (((b * NCH + c) * 64 + (ok ? gr : 0)) * 64 + (ok ? gw : 0));
            cpa4(smb + OFF_X + (uint32_t)(buf * 544 + i) * 4, src, ok);
        }
        const uint4* srcw = (const uint4*)(g_W16 + (2 * j) * NOUT * KPAD);
        #pragma unroll
        for (int i = tid; i < 1024; i += 512)       // 2 ch x 8KB
            cpa16(smb + OFF_B + buf * 16384 + (uint32_t)i * 16, srcw + i);
    };

    stage(0);
    asm volatile("cp.async.commit_group;" ::: "memory");

    // ldmatrix lane offsets within a 16KB A block / 8KB B block
    uint32_t a_off[2];
    #pragma unroll
    for (int mt = 0; mt < 2; ++mt)
        a_off[mt] = (uint32_t)((mrow * 32 + mt * 16 + (lane & 15)) * 128 +
                               (lane >> 4) * 16);
    const uint32_t b_off = (uint32_t)((ncol * 16 + (lane & 15)) * 128 +
                                      (lane >> 4) * 16);

    for (int j = 0; j < NCH / 2; ++j) {
        asm volatile("cp.async.wait_group 0;" ::: "memory");
        __syncthreads();   // x[j], B[j] ready; A[j&1] free (barrier of j-1)

        if (j + 1 < NCH / 2) stage(j + 1);
        asm volatile("cp.async.commit_group;" ::: "memory");

        const uint32_t abuf = smb + OFF_A + (uint32_t)(j & 1) * 32768;
        const uint32_t bbuf = smb + OFF_B + (uint32_t)(j & 1) * 16384;

        // ---- features for both channels of this pair ----
        #pragma unroll
        for (int p = 0; p < 2; ++p) {
            const float* xbp =
                (const float*)(smdyn + OFF_X) + (j & 1) * 544 + p * 272;
            float t[9];
            #pragma unroll
            for (int rr = 0; rr < 3; ++rr)
                #pragma unroll
                for (int dx = 0; dx < 3; ++dx)
                    t[rr * 3 + dx] = xbp[(ry + rr) * 68 + wcol + dx];

            float fl[16];
            switch (h) {   // uniform per warp -> no divergence
                case 0: gen_quarter<0>(t, fl); break;
                case 1: gen_quarter<1>(t, fl); break;
                case 2: gen_quarter<2>(t, fl); break;
                default: gen_quarter<3>(t, fl); break;
            }

            // 16 features = 2 x 16B chunks at bytes [32h, 32h+32) of row m
            uint32_t r[8];
            #pragma unroll
            for (int u = 0; u < 8; ++u) {
                __half2 hh = __floats2half2_rn(fl[2 * u], fl[2 * u + 1]);
                r[u] = *reinterpret_cast<uint32_t*>(&hh);
            }
            const uint32_t ab = abuf + (uint32_t)p * 16384;
            uint32_t o0 = swz((uint32_t)(m * 128 + h * 32));
            uint32_t o1 = swz((uint32_t)(m * 128 + h * 32 + 16));
            asm volatile("st.shared.v4.b32 [%0], {%1,%2,%3,%4};"
                         :: "r"(ab + o0), "r"(r[0]), "r"(r[1]), "r"(r[2]),
                            "r"(r[3]) : "memory");
            asm volatile("st.shared.v4.b32 [%0], {%1,%2,%3,%4};"
                         :: "r"(ab + o1), "r"(r[4]), "r"(r[5]), "r"(r[6]),
                            "r"(r[7]) : "memory");
        }
        __syncthreads();   // A pair ready

        // ---- HMMA over K = 128 (8 k-steps across 2 channel blocks) ----
        #pragma unroll
        for (int ks = 0; ks < 8; ++ks) {
            const uint32_t kh = (uint32_t)(ks >> 2);
            const uint32_t kl = (uint32_t)(ks & 3) * 32;
            const uint32_t Ab = abuf + kh * 16384;
            const uint32_t Bb = bbuf + kh * 8192;
            uint32_t a0[4], a1[4], bb[4];
            ldsm4(a0[0], a0[1], a0[2], a0[3], Ab + swz(a_off[0] + kl));
            ldsm4(a1[0], a1[1], a1[2], a1[3], Ab + swz(a_off[1] + kl));
            ldsm4(bb[0], bb[1], bb[2], bb[3], Bb + swz(b_off + kl));

            mma16816(acc[0][0][0], acc[0][0][1], acc[0][0][2], acc[0][0][3],
                     a0[0], a0[1], a0[2], a0[3], bb[0], bb[2]);
            mma16816(acc[0][1][0], acc[0][1][1], acc[0][1][2], acc[0][1][3],
                     a0[0], a0[1], a0[2], a0[3], bb[1], bb[3]);
            mma16816(acc[1][0][0], acc[1][0][1], acc[1][0][2], acc[1][0][3],
                     a1[0], a1[1], a1[2], a1[3], bb[0], bb[2]);
            mma16816(acc[1][1][0], acc[1][1][1], acc[1][1][2], acc[1][1][3],
                     a1[0], a1[1], a1[2], a1[3], bb[1], bb[3]);
        }
    }

    // ---- epilogue: c-frag -> global, + bias ----
    const int obase = ncol * 16 + (lane & 3) * 2;
    float2 bias2v[2];
    #pragma unroll
    for (int n8 = 0; n8 < 2; ++n8)
        bias2v[n8] = *(const float2*)(g_bias2 + obase + n8 * 8);

    #pragma unroll
    for (int mt = 0; mt < 2; ++mt) {
        #pragma unroll
        for (int half = 0; half < 2; ++half) {
            const int mm = mrow * 32 + mt * 16 + (lane >> 2) + half * 8;
            const int rr = r0 + (mm >> 6), cc = mm & 63;
            float* op = out + ((b * NOUT) * 64 + rr) * 64 + cc;
            #pragma unroll
            for (int n8 = 0; n8 < 2; ++n8) {
                const int o = obase + n8 * 8;
                op[(o)     * 4096] = acc[mt][n8][half * 2]     + bias2v[n8].x;
                op[(o + 1) * 4096] = acc[mt][n8][half * 2 + 1] + bias2v[n8].y;
            }
        }
    }
}

// ---------------------------------------------------------------------------
extern "C" void kernel_launch(void* const* d_in, const int* in_sizes, int n_in,
                              void* d_out, int out_size) {
    const float* x       = (const float*)d_in[0];  // [4,64,64,64]
    const float* filters = (const float*)d_in[1];  // [64,64,10,10]
    const float* biases  = (const float*)d_in[2];  // [64,1]
    float* out = (float*)d_out;                    // [4,64,64,64]
    (void)in_sizes; (void)n_in; (void)out_size;

    static int attr_set = 0;
    if (!attr_set) {
        cudaFuncSetAttribute(poly_mma,
                             cudaFuncAttributeMaxDynamicSharedMemorySize,
                             SMEM_SZ);
        attr_set = 1;
    }
    poly_prep<<<64, 64>>>(filters, biases);
    poly_mma<<<128, 512, SMEM_SZ>>>(x, out);
}

// round 8
// speedup vs baseline: 1.0615x; 1.0615x over previous
#include <cuda_runtime.h>
#include <cuda_fp16.h>
#include <cstdint>

// ---------------------------------------------------------------------------
// Poly2d via warp-level HMMA (mma.sync m16n8k16, fp16 in / fp32 acc).
// 54 features/channel (9 linear + 45 symmetric pairs) padded to 64; const
// term folded into bias. Round 8: Round-6 tiling (4x2 warp grid, 256 thr,
// channel-pair iters) + B-fragment register prefetch in the featgen phase
// so the MMA phase is tensor-bound, + coalesced prep kernel.
// ---------------------------------------------------------------------------

#define NCH   64
#define NOUT  64
#define KPAD  64

__device__ __align__(16) unsigned short g_W16[NCH * NOUT * KPAD];
__device__ float g_bias2[NOUT];

// dynamic smem layout (bytes)
#define OFF_A   0                         // 2 buf x (2 ch x 16384) = 65536
#define OFF_B   65536                     // 2 buf x (2 ch x 8192)  = 32768
#define OFF_X   (OFF_B + 32768)           // 2 buf x 2 ch x 272 floats = 4352
#define SMEM_SZ (OFF_X + 4352)

__device__ __forceinline__ uint32_t s2u(const void* p) {
    return (uint32_t)__cvta_generic_to_shared(p);
}
__device__ __forceinline__ void cpa4(uint32_t s, const void* g, bool ok) {
    asm volatile("cp.async.ca.shared.global [%0], [%1], 4, %2;\n"
                 :: "r"(s), "l"(g), "r"(ok ? 4 : 0));
}
__device__ __forceinline__ void cpa16(uint32_t s, const void* g) {
    asm volatile("cp.async.cg.shared.global [%0], [%1], 16;\n"
                 :: "r"(s), "l"(g));
}
__device__ __forceinline__ uint32_t swz(uint32_t off) {   // SW128
    return off ^ ((off >> 3) & 0x70);
}
__device__ __forceinline__ void ldsm4(uint32_t& r0, uint32_t& r1, uint32_t& r2,
                                      uint32_t& r3, uint32_t addr) {
    asm volatile("ldmatrix.sync.aligned.m8n8.x4.shared.b16 {%0,%1,%2,%3}, [%4];"
                 : "=r"(r0), "=r"(r1), "=r"(r2), "=r"(r3) : "r"(addr));
}
__device__ __forceinline__ void mma16816(float& c0, float& c1, float& c2, float& c3,
                                         uint32_t a0, uint32_t a1, uint32_t a2,
                                         uint32_t a3, uint32_t b0, uint32_t b1) {
    asm volatile(
        "mma.sync.aligned.m16n8k16.row.col.f32.f16.f16.f32 "
        "{%0,%1,%2,%3}, {%4,%5,%6,%7}, {%8,%9}, {%0,%1,%2,%3};"
        : "+f"(c0), "+f"(c1), "+f"(c2), "+f"(c3)
        : "r"(a0), "r"(a1), "r"(a2), "r"(a3), "r"(b0), "r"(b1));
}

// ---------------------------------------------------------------------------
// Prep: pack symmetric weights -> fp16, SW128 pre-applied; fold const term
// into bias. block = channel (64 blocks x 256 threads). Filters slice is
// staged through smem with LINEAR (coalesced) loads, then packed.
// ---------------------------------------------------------------------------
__global__ void __launch_bounds__(256)
poly_prep(const float* __restrict__ filters, const float* __restrict__ biases) {
    __shared__ float fsm[NOUT * 100];                   // 25.6KB: F[o][t], c fixed
    __shared__ __align__(16) unsigned short wsm[NOUT * KPAD];  // 8KB
    const int c = blockIdx.x, tid = threadIdx.x;

    // coalesced load of filters[:, c, :, :]
    for (int i = tid; i < NOUT * 100; i += 256)
        fsm[i] = filters[(i / 100) * 6400 + c * 100 + (i % 100)];
    __syncthreads();

    if (tid < NOUT) {
        const int o = tid;
        const float* F = fsm + o * 100;
        float v[KPAD];
        int k = 0;
        #pragma unroll
        for (int t = 1; t <= 9; ++t) v[k++] = F[t] + F[t * 10];
        #pragma unroll
        for (int i = 1; i <= 9; ++i)
            #pragma unroll
            for (int j = i; j <= 9; ++j)
                v[k++] = (i == j) ? F[i * 10 + i]
                                  : (F[i * 10 + j] + F[j * 10 + i]);
        #pragma unroll
        for (; k < KPAD; ++k) v[k] = 0.0f;

        #pragma unroll
        for (int kk = 0; kk < KPAD; ++kk)
            wsm[swz((uint32_t)(o * 128 + kk * 2)) >> 1] =
                __half_as_ushort(__float2half_rn(v[kk]));

        if (c == 0) {
            float s = biases[o];
            for (int cc = 0; cc < NCH; ++cc) s += filters[o * 6400 + cc * 100];
            g_bias2[o] = s;
        }
    }
    __syncthreads();
    uint4* dst = (uint4*)(g_W16 + c * NOUT * KPAD);
    const uint4* srcp = (const uint4*)wsm;
    for (int i = tid; i < 512; i += 256) dst[i] = srcp[i];
}

// ---------------------------------------------------------------------------
// Main kernel: 128 CTAs (b, row-pair) x 256 threads (8 warps).
// Warp grid 4x2 over D[128 px, 64 o]; iter = 2 channels (K=128).
// B fragments prefetched to registers during the featgen phase.
// ---------------------------------------------------------------------------
extern __shared__ unsigned char smdyn[];

__global__ void __launch_bounds__(256, 1)
poly_mma(const float* __restrict__ x, float* __restrict__ out) {
    const uint32_t smb = s2u(smdyn);
    const int tid = threadIdx.x, lane = tid & 31, wid = tid >> 5;
    const int m = tid & 127, h = tid >> 7;
    const int ry = m >> 6, wcol = m & 63;
    const int mrow = wid >> 1, ncol = wid & 1;
    const int b = blockIdx.x >> 5;
    const int r0 = (blockIdx.x & 31) * 2;

    float acc[2][4][4];
    #pragma unroll
    for (int mt = 0; mt < 2; ++mt)
        #pragma unroll
        for (int n8 = 0; n8 < 4; ++n8)
            #pragma unroll
            for (int q = 0; q < 4; ++q) acc[mt][n8][q] = 0.0f;

    auto stage = [&](int j) {
        const uint32_t buf = (uint32_t)(j & 1);
        #pragma unroll
        for (int i = tid; i < 544; i += 256) {      // 2 ch x 4 rows x 68 cols
            const int p = i / 272, rem = i % 272;
            const int rr = rem / 68, col = rem % 68;
            const int gr = r0 - 1 + rr, gw = col - 1;
            const bool ok = ((unsigned)gr < 64u) && ((unsigned)gw < 64u);
            const int c = 2 * j + p;
            const float* src =
                x + (((b * NCH + c) * 64 + (ok ? gr : 0)) * 64 + (ok ? gw : 0));
            cpa4(smb + OFF_X + (uint32_t)(buf * 544 + i) * 4, src, ok);
        }
        const uint4* srcw = (const uint4*)(g_W16 + (2 * j) * NOUT * KPAD);
        #pragma unroll
        for (int i = tid; i < 1024; i += 256)       // 2 ch x 8KB
            cpa16(smb + OFF_B + buf * 16384 + (uint32_t)i * 16, srcw + i);
    };

    stage(0);
    asm volatile("cp.async.commit_group;" ::: "memory");

    // ldmatrix lane offsets within a 16KB A block / 8KB B block
    uint32_t a_off[2], b_off[2];
    #pragma unroll
    for (int mt = 0; mt < 2; ++mt)
        a_off[mt] = (uint32_t)((mrow * 32 + mt * 16 + (lane & 15)) * 128 +
                               (lane >> 4) * 16);
    #pragma unroll
    for (int nt = 0; nt < 2; ++nt)
        b_off[nt] = (uint32_t)((ncol * 32 + nt * 16 + (lane & 15)) * 128 +
                               (lane >> 4) * 16);

    for (int j = 0; j < NCH / 2; ++j) {
        asm volatile("cp.async.wait_group 0;" ::: "memory");
        __syncthreads();   // x[j], B[j] ready; A[j&1] free (barrier of j-1)

        if (j + 1 < NCH / 2) stage(j + 1);
        asm volatile("cp.async.commit_group;" ::: "memory");

        const uint32_t abuf = smb + OFF_A + (uint32_t)(j & 1) * 32768;
        const uint32_t bbuf = smb + OFF_B + (uint32_t)(j & 1) * 16384;

        // ---- B fragment prefetch (smem latency hides behind featgen) ----
        uint32_t bf[8][8];
        #pragma unroll
        for (int ks = 0; ks < 8; ++ks) {
            const uint32_t kh = (uint32_t)(ks >> 2);
            const uint32_t kl = (uint32_t)(ks & 3) * 32;
            const uint32_t Bb = bbuf + kh * 8192;
            ldsm4(bf[ks][0], bf[ks][1], bf[ks][2], bf[ks][3],
                  Bb + swz(b_off[0] + kl));
            ldsm4(bf[ks][4], bf[ks][5], bf[ks][6], bf[ks][7],
                  Bb + swz(b_off[1] + kl));
        }

        // ---- features for both channels of this pair ----
        #pragma unroll
        for (int p = 0; p < 2; ++p) {
            const float* xbp =
                (const float*)(smdyn + OFF_X) + (j & 1) * 544 + p * 272;
            float t[9];
            #pragma unroll
            for (int rr = 0; rr < 3; ++rr)
                #pragma unroll
                for (int dx = 0; dx < 3; ++dx)
                    t[rr * 3 + dx] = xbp[(ry + rr) * 68 + wcol + dx];

            float fl[32];
            if (h == 0) {
                #pragma unroll
                for (int tt = 0; tt < 9; ++tt) fl[tt] = t[tt];
                int k = 9;
                #pragma unroll
                for (int i = 0; i < 9; ++i)
                    #pragma unroll
                    for (int jj = i; jj < 9; ++jj) {
                        if (k < 32) fl[k] = t[i] * t[jj];
                        ++k;
                    }
            } else {
                int k = 9;
                #pragma unroll
                for (int i = 0; i < 9; ++i)
                    #pragma unroll
                    for (int jj = i; jj < 9; ++jj) {
                        if (k >= 32 && k < 54) fl[k - 32] = t[i] * t[jj];
                        ++k;
                    }
                #pragma unroll
                for (int z = 22; z < 32; ++z) fl[z] = 0.0f;
            }

            #pragma unroll
            for (int q = 0; q < 4; ++q) {
                uint32_t r[4];
                #pragma unroll
                for (int u = 0; u < 4; ++u) {
                    __half2 hh = __floats2half2_rn(fl[q * 8 + 2 * u],
                                                   fl[q * 8 + 2 * u + 1]);
                    r[u] = *reinterpret_cast<uint32_t*>(&hh);
                }
                uint32_t off = swz((uint32_t)(m * 128 + h * 64 + q * 16));
                asm volatile("st.shared.v4.b32 [%0], {%1,%2,%3,%4};"
                             :: "r"(abuf + (uint32_t)p * 16384 + off),
                                "r"(r[0]), "r"(r[1]), "r"(r[2]), "r"(r[3])
                             : "memory");
            }
        }
        __syncthreads();   // A pair ready

        // ---- MMA phase: only A-ldsm + HMMA (B already in registers) ----
        #pragma unroll
        for (int ks = 0; ks < 8; ++ks) {
            const uint32_t kh = (uint32_t)(ks >> 2);
            const uint32_t kl = (uint32_t)(ks & 3) * 32;
            const uint32_t Ab = abuf + kh * 16384;
            uint32_t a0[4], a1[4];
            ldsm4(a0[0], a0[1], a0[2], a0[3], Ab + swz(a_off[0] + kl));
            ldsm4(a1[0], a1[1], a1[2], a1[3], Ab + swz(a_off[1] + kl));

            mma16816(acc[0][0][0], acc[0][0][1], acc[0][0][2], acc[0][0][3],
                     a0[0], a0[1], a0[2], a0[3], bf[ks][0], bf[ks][2]);
            mma16816(acc[0][1][0], acc[0][1][1], acc[0][1][2], acc[0][1][3],
                     a0[0], a0[1], a0[2], a0[3], bf[ks][1], bf[ks][3]);
            mma16816(acc[0][2][0], acc[0][2][1], acc[0][2][2], acc[0][2][3],
                     a0[0], a0[1], a0[2], a0[3], bf[ks][4], bf[ks][6]);
            mma16816(acc[0][3][0], acc[0][3][1], acc[0][3][2], acc[0][3][3],
                     a0[0], a0[1], a0[2], a0[3], bf[ks][5], bf[ks][7]);
            mma16816(acc[1][0][0], acc[1][0][1], acc[1][0][2], acc[1][0][3],
                     a1[0], a1[1], a1[2], a1[3], bf[ks][0], bf[ks][2]);
            mma16816(acc[1][1][0], acc[1][1][1], acc[1][1][2], acc[1][1][3],
                     a1[0], a1[1], a1[2], a1[3], bf[ks][1], bf[ks][3]);
            mma16816(acc[1][2][0], acc[1][2][1], acc[1][2][2], acc[1][2][3],
                     a1[0], a1[1], a1[2], a1[3], bf[ks][4], bf[ks][6]);
            mma16816(acc[1][3][0], acc[1][3][1], acc[1][3][2], acc[1][3][3],
                     a1[0], a1[1], a1[2], a1[3], bf[ks][5], bf[ks][7]);
        }
    }

    // ---- epilogue: c-frag -> global, + bias ----
    const int obase = ncol * 32 + (lane & 3) * 2;
    float2 bias2v[4];
    #pragma unroll
    for (int n8 = 0; n8 < 4; ++n8)
        bias2v[n8] = *(const float2*)(g_bias2 + obase + n8 * 8);

    #pragma unroll
    for (int mt = 0; mt < 2; ++mt) {
        #pragma unroll
        for (int half = 0; half < 2; ++half) {
            const int mm = mrow * 32 + mt * 16 + (lane >> 2) + half * 8;
            const int rr = r0 + (mm >> 6), cc = mm & 63;
            float* op = out + ((b * NOUT) * 64 + rr) * 64 + cc;
            #pragma unroll
            for (int n8 = 0; n8 < 4; ++n8) {
                const int o = obase + n8 * 8;
                op[(o)     * 4096] = acc[mt][n8][half * 2]     + bias2v[n8].x;
                op[(o + 1) * 4096] = acc[mt][n8][half * 2 + 1] + bias2v[n8].y;
            }
        }
    }
}

// ---------------------------------------------------------------------------
extern "C" void kernel_launch(void* const* d_in, const int* in_sizes, int n_in,
                              void* d_out, int out_size) {
    const float* x       = (const float*)d_in[0];  // [4,64,64,64]
    const float* filters = (const float*)d_in[1];  // [64,64,10,10]
    const float* biases  = (const float*)d_in[2];  // [64,1]
    float* out = (float*)d_out;                    // [4,64,64,64]
    (void)in_sizes; (void)n_in; (void)out_size;

    static int attr_set = 0;
    if (!attr_set) {
        cudaFuncSetAttribute(poly_mma,
                             cudaFuncAttributeMaxDynamicSharedMemorySize,
                             SMEM_SZ);
        attr_set = 1;
    }
    poly_prep<<<64, 256>>>(filters, biases);
    poly_mma<<<128, 256, SMEM_SZ>>>(x, out);
}

// round 9
// speedup vs baseline: 1.1336x; 1.0680x over previous
#include <cuda_runtime.h>
#include <cuda_fp16.h>
#include <cstdint>

// ---------------------------------------------------------------------------
// Poly2d via warp-level HMMA (mma.sync m16n8k16, fp16 in / fp32 acc).
// 54 features/channel (9 linear + 45 symmetric pairs) padded to 64; const
// term folded into bias. Round 9: FUSED mainloop — iter j does MMA(pair j)
// + featgen(pair j+1) + stage(pair j+2) in one block with ONE barrier per
// iter, so tensor and fma pipes overlap. A double-buffer, B ring-of-3.
// ---------------------------------------------------------------------------

#define NCH   64
#define NOUT  64
#define KPAD  64

__device__ __align__(16) unsigned short g_W16[NCH * NOUT * KPAD];
__device__ float g_bias2[NOUT];

// dynamic smem layout (bytes)
#define OFF_A   0                          // 2 buf x (2 ch x 16384) = 65536
#define OFF_B   65536                      // 3 buf x (2 ch x 8192)  = 49152
#define OFF_X   (OFF_B + 49152)            // 2 buf x 544 floats     = 4352
#define SMEM_SZ (OFF_X + 4352)

__device__ __forceinline__ uint32_t s2u(const void* p) {
    return (uint32_t)__cvta_generic_to_shared(p);
}
__device__ __forceinline__ void cpa4(uint32_t s, const void* g, bool ok) {
    asm volatile("cp.async.ca.shared.global [%0], [%1], 4, %2;\n"
                 :: "r"(s), "l"(g), "r"(ok ? 4 : 0));
}
__device__ __forceinline__ void cpa16(uint32_t s, const void* g) {
    asm volatile("cp.async.cg.shared.global [%0], [%1], 16;\n"
                 :: "r"(s), "l"(g));
}
__device__ __forceinline__ uint32_t swz(uint32_t off) {   // SW128
    return off ^ ((off >> 3) & 0x70);
}
__device__ __forceinline__ void ldsm4(uint32_t& r0, uint32_t& r1, uint32_t& r2,
                                      uint32_t& r3, uint32_t addr) {
    asm volatile("ldmatrix.sync.aligned.m8n8.x4.shared.b16 {%0,%1,%2,%3}, [%4];"
                 : "=r"(r0), "=r"(r1), "=r"(r2), "=r"(r3) : "r"(addr));
}
__device__ __forceinline__ void mma16816(float& c0, float& c1, float& c2, float& c3,
                                         uint32_t a0, uint32_t a1, uint32_t a2,
                                         uint32_t a3, uint32_t b0, uint32_t b1) {
    asm volatile(
        "mma.sync.aligned.m16n8k16.row.col.f32.f16.f16.f32 "
        "{%0,%1,%2,%3}, {%4,%5,%6,%7}, {%8,%9}, {%0,%1,%2,%3};"
        : "+f"(c0), "+f"(c1), "+f"(c2), "+f"(c3)
        : "r"(a0), "r"(a1), "r"(a2), "r"(a3), "r"(b0), "r"(b1));
}

// ---------------------------------------------------------------------------
// Prep: pack symmetric weights -> fp16, SW128 pre-applied; fold const term
// into bias. block = channel; filters slice staged coalesced through smem.
// ---------------------------------------------------------------------------
__global__ void __launch_bounds__(256)
poly_prep(const float* __restrict__ filters, const float* __restrict__ biases) {
    __shared__ float fsm[NOUT * 100];
    __shared__ __align__(16) unsigned short wsm[NOUT * KPAD];
    const int c = blockIdx.x, tid = threadIdx.x;

    for (int i = tid; i < NOUT * 100; i += 256)
        fsm[i] = filters[(i / 100) * 6400 + c * 100 + (i % 100)];
    __syncthreads();

    if (tid < NOUT) {
        const int o = tid;
        const float* F = fsm + o * 100;
        float v[KPAD];
        int k = 0;
        #pragma unroll
        for (int t = 1; t <= 9; ++t) v[k++] = F[t] + F[t * 10];
        #pragma unroll
        for (int i = 1; i <= 9; ++i)
            #pragma unroll
            for (int j = i; j <= 9; ++j)
                v[k++] = (i == j) ? F[i * 10 + i]
                                  : (F[i * 10 + j] + F[j * 10 + i]);
        #pragma unroll
        for (; k < KPAD; ++k) v[k] = 0.0f;

        #pragma unroll
        for (int kk = 0; kk < KPAD; ++kk)
            wsm[swz((uint32_t)(o * 128 + kk * 2)) >> 1] =
                __half_as_ushort(__float2half_rn(v[kk]));

        if (c == 0) {
            float s = biases[o];
            for (int cc = 0; cc < NCH; ++cc) s += filters[o * 6400 + cc * 100];
            g_bias2[o] = s;
        }
    }
    __syncthreads();
    uint4* dst = (uint4*)(g_W16 + c * NOUT * KPAD);
    const uint4* srcp = (const uint4*)wsm;
    for (int i = tid; i < 512; i += 256) dst[i] = srcp[i];
}

// ---------------------------------------------------------------------------
// Main kernel: 128 CTAs (b, row-pair) x 256 threads (8 warps), 4x2 warp grid.
// Fused loop: iter j = MMA(pair j) + featgen(pair j+1) + stage(pair j+2).
// ---------------------------------------------------------------------------
extern __shared__ unsigned char smdyn[];

__global__ void __launch_bounds__(256, 1)
poly_mma(const float* __restrict__ x, float* __restrict__ out) {
    const uint32_t smb = s2u(smdyn);
    const int tid = threadIdx.x, lane = tid & 31, wid = tid >> 5;
    const int m = tid & 127, h = tid >> 7;
    const int ry = m >> 6, wcol = m & 63;
    const int mrow = wid >> 1, ncol = wid & 1;
    const int b = blockIdx.x >> 5;
    const int r0 = (blockIdx.x & 31) * 2;

    float acc[2][4][4];
    #pragma unroll
    for (int mt = 0; mt < 2; ++mt)
        #pragma unroll
        for (int n8 = 0; n8 < 4; ++n8)
            #pragma unroll
            for (int q = 0; q < 4; ++q) acc[mt][n8][q] = 0.0f;

    // stage pair j: x -> xbuf (j&1), weights -> Bbuf (j%3)
    auto stage = [&](int j) {
        const uint32_t xb = (uint32_t)(j & 1);
        const uint32_t bb = (uint32_t)(j % 3);
        #pragma unroll
        for (int i = tid; i < 544; i += 256) {      // 2 ch x 4 rows x 68 cols
            const int p = i / 272, rem = i % 272;
            const int rr = rem / 68, col = rem % 68;
            const int gr = r0 - 1 + rr, gw = col - 1;
            const bool ok = ((unsigned)gr < 64u) && ((unsigned)gw < 64u);
            const int c = 2 * j + p;
            const float* src =
                x + (((b * NCH + c) * 64 + (ok ? gr : 0)) * 64 + (ok ? gw : 0));
            cpa4(smb + OFF_X + (xb * 544 + (uint32_t)i) * 4, src, ok);
        }
        const uint4* srcw = (const uint4*)(g_W16 + (2 * j) * NOUT * KPAD);
        #pragma unroll
        for (int i = tid; i < 1024; i += 256)       // 2 ch x 8KB
            cpa16(smb + OFF_B + bb * 16384 + (uint32_t)i * 16, srcw + i);
    };

    // featgen pair j -> A buf (j&1)
    auto featgen = [&](int j) {
        const uint32_t abuf = smb + OFF_A + (uint32_t)(j & 1) * 32768;
        #pragma unroll
        for (int p = 0; p < 2; ++p) {
            const float* xbp =
                (const float*)(smdyn + OFF_X) + (j & 1) * 544 + p * 272;
            float t[9];
            #pragma unroll
            for (int rr = 0; rr < 3; ++rr)
                #pragma unroll
                for (int dx = 0; dx < 3; ++dx)
                    t[rr * 3 + dx] = xbp[(ry + rr) * 68 + wcol + dx];

            float fl[32];
            if (h == 0) {
                #pragma unroll
                for (int tt = 0; tt < 9; ++tt) fl[tt] = t[tt];
                int k = 9;
                #pragma unroll
                for (int i = 0; i < 9; ++i)
                    #pragma unroll
                    for (int jj = i; jj < 9; ++jj) {
                        if (k < 32) fl[k] = t[i] * t[jj];
                        ++k;
                    }
            } else {
                int k = 9;
                #pragma unroll
                for (int i = 0; i < 9; ++i)
                    #pragma unroll
                    for (int jj = i; jj < 9; ++jj) {
                        if (k >= 32 && k < 54) fl[k - 32] = t[i] * t[jj];
                        ++k;
                    }
                #pragma unroll
                for (int z = 22; z < 32; ++z) fl[z] = 0.0f;
            }

            #pragma unroll
            for (int q = 0; q < 4; ++q) {
                uint32_t r[4];
                #pragma unroll
                for (int u = 0; u < 4; ++u) {
                    __half2 hh = __floats2half2_rn(fl[q * 8 + 2 * u],
                                                   fl[q * 8 + 2 * u + 1]);
                    r[u] = *reinterpret_cast<uint32_t*>(&hh);
                }
                uint32_t off = swz((uint32_t)(m * 128 + h * 64 + q * 16));
                asm volatile("st.shared.v4.b32 [%0], {%1,%2,%3,%4};"
                             :: "r"(abuf + (uint32_t)p * 16384 + off),
                                "r"(r[0]), "r"(r[1]), "r"(r[2]), "r"(r[3])
                             : "memory");
            }
        }
    };

    // ldmatrix lane offsets within a 16KB A block / 8KB B block
    uint32_t a_off[2], b_off[2];
    #pragma unroll
    for (int mt = 0; mt < 2; ++mt)
        a_off[mt] = (uint32_t)((mrow * 32 + mt * 16 + (lane & 15)) * 128 +
                               (lane >> 4) * 16);
    #pragma unroll
    for (int nt = 0; nt < 2; ++nt)
        b_off[nt] = (uint32_t)((ncol * 32 + nt * 16 + (lane & 15)) * 128 +
                               (lane >> 4) * 16);

    // ---- prologue ----
    stage(0);
    asm volatile("cp.async.commit_group;" ::: "memory");
    asm volatile("cp.async.wait_group 0;" ::: "memory");
    __syncthreads();
    featgen(0);
    stage(1);
    asm volatile("cp.async.commit_group;" ::: "memory");

    // ---- fused mainloop: one barrier per channel pair ----
    for (int j = 0; j < NCH / 2; ++j) {
        asm volatile("cp.async.wait_group 0;" ::: "memory");  // stage(j+1) done
        __syncthreads();   // A[j] visible; all readers of A[(j+1)&1],
                           // B[(j+2)%3], x[j&1] finished last iter

        if (j + 2 < NCH / 2) {
            stage(j + 2);
            asm volatile("cp.async.commit_group;" ::: "memory");
        }

        if (j + 1 < NCH / 2) featgen(j + 1);

        // MMA(pair j): A buf j&1, B buf j%3  (interleaves with featgen above)
        const uint32_t abuf = smb + OFF_A + (uint32_t)(j & 1) * 32768;
        const uint32_t bbuf = smb + OFF_B + (uint32_t)(j % 3) * 16384;
        #pragma unroll
        for (int ks = 0; ks < 8; ++ks) {
            const uint32_t kh = (uint32_t)(ks >> 2);
            const uint32_t kl = (uint32_t)(ks & 3) * 32;
            const uint32_t Ab = abuf + kh * 16384;
            const uint32_t Bb = bbuf + kh * 8192;
            uint32_t a0[4], a1[4], bA[4], bB[4];
            ldsm4(a0[0], a0[1], a0[2], a0[3], Ab + swz(a_off[0] + kl));
            ldsm4(a1[0], a1[1], a1[2], a1[3], Ab + swz(a_off[1] + kl));
            ldsm4(bA[0], bA[1], bA[2], bA[3], Bb + swz(b_off[0] + kl));
            ldsm4(bB[0], bB[1], bB[2], bB[3], Bb + swz(b_off[1] + kl));

            mma16816(acc[0][0][0], acc[0][0][1], acc[0][0][2], acc[0][0][3],
                     a0[0], a0[1], a0[2], a0[3], bA[0], bA[2]);
            mma16816(acc[0][1][0], acc[0][1][1], acc[0][1][2], acc[0][1][3],
                     a0[0], a0[1], a0[2], a0[3], bA[1], bA[3]);
            mma16816(acc[0][2][0], acc[0][2][1], acc[0][2][2], acc[0][2][3],
                     a0[0], a0[1], a0[2], a0[3], bB[0], bB[2]);
            mma16816(acc[0][3][0], acc[0][3][1], acc[0][3][2], acc[0][3][3],
                     a0[0], a0[1], a0[2], a0[3], bB[1], bB[3]);
            mma16816(acc[1][0][0], acc[1][0][1], acc[1][0][2], acc[1][0][3],
                     a1[0], a1[1], a1[2], a1[3], bA[0], bA[2]);
            mma16816(acc[1][1][0], acc[1][1][1], acc[1][1][2], acc[1][1][3],
                     a1[0], a1[1], a1[2], a1[3], bA[1], bA[3]);
            mma16816(acc[1][2][0], acc[1][2][1], acc[1][2][2], acc[1][2][3],
                     a1[0], a1[1], a1[2], a1[3], bB[0], bB[2]);
            mma16816(acc[1][3][0], acc[1][3][1], acc[1][3][2], acc[1][3][3],
                     a1[0], a1[1], a1[2], a1[3], bB[1], bB[3]);
        }
    }

    // ---- epilogue: c-frag -> global, + bias ----
    const int obase = ncol * 32 + (lane & 3) * 2;
    float2 bias2v[4];
    #pragma unroll
    for (int n8 = 0; n8 < 4; ++n8)
        bias2v[n8] = *(const float2*)(g_bias2 + obase + n8 * 8);

    #pragma unroll
    for (int mt = 0; mt < 2; ++mt) {
        #pragma unroll
        for (int half = 0; half < 2; ++half) {
            const int mm = mrow * 32 + mt * 16 + (lane >> 2) + half * 8;
            const int rr = r0 + (mm >> 6), cc = mm & 63;
            float* op = out + ((b * NOUT) * 64 + rr) * 64 + cc;
            #pragma unroll
            for (int n8 = 0; n8 < 4; ++n8) {
                const int o = obase + n8 * 8;
                op[(o)     * 4096] = acc[mt][n8][half * 2]     + bias2v[n8].x;
                op[(o + 1) * 4096] = acc[mt][n8][half * 2 + 1] + bias2v[n8].y;
            }
        }
    }
}

// ---------------------------------------------------------------------------
extern "C" void kernel_launch(void* const* d_in, const int* in_sizes, int n_in,
                              void* d_out, int out_size) {
    const float* x       = (const float*)d_in[0];  // [4,64,64,64]
    const float* filters = (const float*)d_in[1];  // [64,64,10,10]
    const float* biases  = (const float*)d_in[2];  // [64,1]
    float* out = (float*)d_out;                    // [4,64,64,64]
    (void)in_sizes; (void)n_in; (void)out_size;

    static int attr_set = 0;
    if (!attr_set) {
        cudaFuncSetAttribute(poly_mma,
                             cudaFuncAttributeMaxDynamicSharedMemorySize,
                             SMEM_SZ);
        attr_set = 1;
    }
    poly_prep<<<64, 256>>>(filters, biases);
    poly_mma<<<128, 256, SMEM_SZ>>>(x, out);
}

// round 10
// speedup vs baseline: 1.1922x; 1.0517x over previous
#include <cuda_runtime.h>
#include <cuda_fp16.h>
#include <cstdint>

// ---------------------------------------------------------------------------
// Poly2d via warp-level HMMA (mma.sync m16n8k16, fp16 in / fp32 acc).
// 54 features/channel (9 linear + 45 symmetric pairs) padded to 64; const
// term folded into bias. Round 10: 2 CTAs per SM — M=64 tile, 256 CTAs x
// 128 threads (2x2 warp grid, 32x32 warp tiles). Same per-warp traffic as
// the best config, but the two co-resident CTAs have independent barriers
// so one CTA's MMA overlaps the other's featgen/sync.
// ---------------------------------------------------------------------------

#define NCH   64
#define NOUT  64
#define KPAD  64

__device__ __align__(16) unsigned short g_W16[NCH * NOUT * KPAD];
__device__ float g_bias2[NOUT];

// dynamic smem layout (bytes)
#define OFF_A   0                          // 2 buf x (2 ch x 8192)  = 32768
#define OFF_B   32768                      // 2 buf x (2 ch x 8192)  = 32768
#define OFF_X   (OFF_B + 32768)            // 2 buf x 2 ch x 204 floats = 3264
#define SMEM_SZ (OFF_X + 3264 + 64)

__device__ __forceinline__ uint32_t s2u(const void* p) {
    return (uint32_t)__cvta_generic_to_shared(p);
}
__device__ __forceinline__ void cpa4(uint32_t s, const void* g, bool ok) {
    asm volatile("cp.async.ca.shared.global [%0], [%1], 4, %2;\n"
                 :: "r"(s), "l"(g), "r"(ok ? 4 : 0));
}
__device__ __forceinline__ void cpa16(uint32_t s, const void* g) {
    asm volatile("cp.async.cg.shared.global [%0], [%1], 16;\n"
                 :: "r"(s), "l"(g));
}
__device__ __forceinline__ uint32_t swz(uint32_t off) {   // SW128
    return off ^ ((off >> 3) & 0x70);
}
__device__ __forceinline__ void ldsm4(uint32_t& r0, uint32_t& r1, uint32_t& r2,
                                      uint32_t& r3, uint32_t addr) {
    asm volatile("ldmatrix.sync.aligned.m8n8.x4.shared.b16 {%0,%1,%2,%3}, [%4];"
                 : "=r"(r0), "=r"(r1), "=r"(r2), "=r"(r3) : "r"(addr));
}
__device__ __forceinline__ void mma16816(float& c0, float& c1, float& c2, float& c3,
                                         uint32_t a0, uint32_t a1, uint32_t a2,
                                         uint32_t a3, uint32_t b0, uint32_t b1) {
    asm volatile(
        "mma.sync.aligned.m16n8k16.row.col.f32.f16.f16.f32 "
        "{%0,%1,%2,%3}, {%4,%5,%6,%7}, {%8,%9}, {%0,%1,%2,%3};"
        : "+f"(c0), "+f"(c1), "+f"(c2), "+f"(c3)
        : "r"(a0), "r"(a1), "r"(a2), "r"(a3), "r"(b0), "r"(b1));
}

// ---------------------------------------------------------------------------
// Prep: pack symmetric weights -> fp16, SW128 pre-applied; fold const term
// into bias. block = channel; filters slice staged coalesced through smem.
// ---------------------------------------------------------------------------
__global__ void __launch_bounds__(256)
poly_prep(const float* __restrict__ filters, const float* __restrict__ biases) {
    __shared__ float fsm[NOUT * 100];
    __shared__ __align__(16) unsigned short wsm[NOUT * KPAD];
    const int c = blockIdx.x, tid = threadIdx.x;

    for (int i = tid; i < NOUT * 100; i += 256)
        fsm[i] = filters[(i / 100) * 6400 + c * 100 + (i % 100)];
    __syncthreads();

    if (tid < NOUT) {
        const int o = tid;
        const float* F = fsm + o * 100;
        float v[KPAD];
        int k = 0;
        #pragma unroll
        for (int t = 1; t <= 9; ++t) v[k++] = F[t] + F[t * 10];
        #pragma unroll
        for (int i = 1; i <= 9; ++i)
            #pragma unroll
            for (int j = i; j <= 9; ++j)
                v[k++] = (i == j) ? F[i * 10 + i]
                                  : (F[i * 10 + j] + F[j * 10 + i]);
        #pragma unroll
        for (; k < KPAD; ++k) v[k] = 0.0f;

        #pragma unroll
        for (int kk = 0; kk < KPAD; ++kk)
            wsm[swz((uint32_t)(o * 128 + kk * 2)) >> 1] =
                __half_as_ushort(__float2half_rn(v[kk]));

        if (c == 0) {
            float s = biases[o];
            for (int cc = 0; cc < NCH; ++cc) s += filters[o * 6400 + cc * 100];
            g_bias2[o] = s;
        }
    }
    __syncthreads();
    uint4* dst = (uint4*)(g_W16 + c * NOUT * KPAD);
    const uint4* srcp = (const uint4*)wsm;
    for (int i = tid; i < 512; i += 256) dst[i] = srcp[i];
}

// ---------------------------------------------------------------------------
// Main kernel: 256 CTAs (b, row) x 128 threads (4 warps), 2x2 warp grid over
// D[64 px, 64 o]; iter = 2 channels (K=128). 2 CTAs co-resident per SM.
// Feature gen: thread = pixel (tid&63) x half (tid>>6).
// ---------------------------------------------------------------------------
extern __shared__ unsigned char smdyn[];

__global__ void __launch_bounds__(128, 2)
poly_mma(const float* __restrict__ x, float* __restrict__ out) {
    const uint32_t smb = s2u(smdyn);
    const int tid = threadIdx.x, lane = tid & 31, wid = tid >> 5;
    const int m = tid & 63, h = tid >> 6;           // pixel col, feature-half
    const int mrow = wid >> 1, ncol = wid & 1;      // 2x2 warp grid
    const int b = blockIdx.x >> 6;
    const int r = blockIdx.x & 63;

    float acc[2][4][4];
    #pragma unroll
    for (int mt = 0; mt < 2; ++mt)
        #pragma unroll
        for (int n8 = 0; n8 < 4; ++n8)
            #pragma unroll
            for (int q = 0; q < 4; ++q) acc[mt][n8][q] = 0.0f;

    // stage channel pair (2j, 2j+1) into buffer j&1
    auto stage = [&](int j) {
        const uint32_t buf = (uint32_t)(j & 1);
        #pragma unroll
        for (int i = tid; i < 408; i += 128) {      // 2 ch x 3 rows x 68 cols
            const int p = i / 204, rem = i % 204;
            const int rr = rem / 68, col = rem % 68;
            const int gr = r - 1 + rr, gw = col - 1;
            const bool ok = ((unsigned)gr < 64u) && ((unsigned)gw < 64u);
            const int c = 2 * j + p;
            const float* src =
                x + (((b * NCH + c) * 64 + (ok ? gr : 0)) * 64 + (ok ? gw : 0));
            cpa4(smb + OFF_X + (buf * 408 + (uint32_t)i) * 4, src, ok);
        }
        const uint4* srcw = (const uint4*)(g_W16 + (2 * j) * NOUT * KPAD);
        #pragma unroll
        for (int i = tid; i < 1024; i += 128)       // 2 ch x 8KB
            cpa16(smb + OFF_B + buf * 16384 + (uint32_t)i * 16, srcw + i);
    };

    stage(0);
    asm volatile("cp.async.commit_group;" ::: "memory");

    // ldmatrix lane offsets within an 8KB (64-row) SW128 block
    uint32_t a_off[2], b_off[2];
    #pragma unroll
    for (int mt = 0; mt < 2; ++mt)
        a_off[mt] = (uint32_t)((mrow * 32 + mt * 16 + (lane & 15)) * 128 +
                               (lane >> 4) * 16);
    #pragma unroll
    for (int nt = 0; nt < 2; ++nt)
        b_off[nt] = (uint32_t)((ncol * 32 + nt * 16 + (lane & 15)) * 128 +
                               (lane >> 4) * 16);

    for (int j = 0; j < NCH / 2; ++j) {
        asm volatile("cp.async.wait_group 0;" ::: "memory");
        __syncthreads();   // x[j], B[j] ready; A[j&1] free (MMA j-2 done)

        if (j + 1 < NCH / 2) stage(j + 1);
        asm volatile("cp.async.commit_group;" ::: "memory");

        const uint32_t abuf = smb + OFF_A + (uint32_t)(j & 1) * 16384;
        const uint32_t bbuf = smb + OFF_B + (uint32_t)(j & 1) * 16384;

        // ---- features for both channels of this pair ----
        #pragma unroll
        for (int p = 0; p < 2; ++p) {
            const float* xbp =
                (const float*)(smdyn + OFF_X) + (j & 1) * 408 + p * 204;
            float t[9];
            #pragma unroll
            for (int rr = 0; rr < 3; ++rr)
                #pragma unroll
                for (int dx = 0; dx < 3; ++dx)
                    t[rr * 3 + dx] = xbp[rr * 68 + m + dx];

            float fl[32];
            if (h == 0) {
                #pragma unroll
                for (int tt = 0; tt < 9; ++tt) fl[tt] = t[tt];
                int k = 9;
                #pragma unroll
                for (int i = 0; i < 9; ++i)
                    #pragma unroll
                    for (int jj = i; jj < 9; ++jj) {
                        if (k < 32) fl[k] = t[i] * t[jj];
                        ++k;
                    }
            } else {
                int k = 9;
                #pragma unroll
                for (int i = 0; i < 9; ++i)
                    #pragma unroll
                    for (int jj = i; jj < 9; ++jj) {
                        if (k >= 32 && k < 54) fl[k - 32] = t[i] * t[jj];
                        ++k;
                    }
                #pragma unroll
                for (int z = 22; z < 32; ++z) fl[z] = 0.0f;
            }

            #pragma unroll
            for (int q = 0; q < 4; ++q) {
                uint32_t rg[4];
                #pragma unroll
                for (int u = 0; u < 4; ++u) {
                    __half2 hh = __floats2half2_rn(fl[q * 8 + 2 * u],
                                                   fl[q * 8 + 2 * u + 1]);
                    rg[u] = *reinterpret_cast<uint32_t*>(&hh);
                }
                uint32_t off = swz((uint32_t)(m * 128 + h * 64 + q * 16));
                asm volatile("st.shared.v4.b32 [%0], {%1,%2,%3,%4};"
                             :: "r"(abuf + (uint32_t)p * 8192 + off),
                                "r"(rg[0]), "r"(rg[1]), "r"(rg[2]), "r"(rg[3])
                             : "memory");
            }
        }
        __syncthreads();   // A pair ready

        // ---- HMMA over K = 128 (8 k-steps across 2 channel blocks) ----
        #pragma unroll
        for (int ks = 0; ks < 8; ++ks) {
            const uint32_t kh = (uint32_t)(ks >> 2);
            const uint32_t kl = (uint32_t)(ks & 3) * 32;
            const uint32_t Ab = abuf + kh * 8192;
            const uint32_t Bb = bbuf + kh * 8192;
            uint32_t a0[4], a1[4], bA[4], bB[4];
            ldsm4(a0[0], a0[1], a0[2], a0[3], Ab + swz(a_off[0] + kl));
            ldsm4(a1[0], a1[1], a1[2], a1[3], Ab + swz(a_off[1] + kl));
            ldsm4(bA[0], bA[1], bA[2], bA[3], Bb + swz(b_off[0] + kl));
            ldsm4(bB[0], bB[1], bB[2], bB[3], Bb + swz(b_off[1] + kl));

            mma16816(acc[0][0][0], acc[0][0][1], acc[0][0][2], acc[0][0][3],
                     a0[0], a0[1], a0[2], a0[3], bA[0], bA[2]);
            mma16816(acc[0][1][0], acc[0][1][1], acc[0][1][2], acc[0][1][3],
                     a0[0], a0[1], a0[2], a0[3], bA[1], bA[3]);
            mma16816(acc[0][2][0], acc[0][2][1], acc[0][2][2], acc[0][2][3],
                     a0[0], a0[1], a0[2], a0[3], bB[0], bB[2]);
            mma16816(acc[0][3][0], acc[0][3][1], acc[0][3][2], acc[0][3][3],
                     a0[0], a0[1], a0[2], a0[3], bB[1], bB[3]);
            mma16816(acc[1][0][0], acc[1][0][1], acc[1][0][2], acc[1][0][3],
                     a1[0], a1[1], a1[2], a1[3], bA[0], bA[2]);
            mma16816(acc[1][1][0], acc[1][1][1], acc[1][1][2], acc[1][1][3],
                     a1[0], a1[1], a1[2], a1[3], bA[1], bA[3]);
            mma16816(acc[1][2][0], acc[1][2][1], acc[1][2][2], acc[1][2][3],
                     a1[0], a1[1], a1[2], a1[3], bB[0], bB[2]);
            mma16816(acc[1][3][0], acc[1][3][1], acc[1][3][2], acc[1][3][3],
                     a1[0], a1[1], a1[2], a1[3], bB[1], bB[3]);
        }
    }

    // ---- epilogue: c-frag -> global, + bias ----
    const int obase = ncol * 32 + (lane & 3) * 2;
    float2 bias2v[4];
    #pragma unroll
    for (int n8 = 0; n8 < 4; ++n8)
        bias2v[n8] = *(const float2*)(g_bias2 + obase + n8 * 8);

    #pragma unroll
    for (int mt = 0; mt < 2; ++mt) {
        #pragma unroll
        for (int half = 0; half < 2; ++half) {
            const int cc = mrow * 32 + mt * 16 + (lane >> 2) + half * 8;
            float* op = out + ((b * NOUT) * 64 + r) * 64 + cc;
            #pragma unroll
            for (int n8 = 0; n8 < 4; ++n8) {
                const int o = obase + n8 * 8;
                op[(o)     * 4096] = acc[mt][n8][half * 2]     + bias2v[n8].x;
                op[(o + 1) * 4096] = acc[mt][n8][half * 2 + 1] + bias2v[n8].y;
            }
        }
    }
}

// ---------------------------------------------------------------------------
extern "C" void kernel_launch(void* const* d_in, const int* in_sizes, int n_in,
                              void* d_out, int out_size) {
    const float* x       = (const float*)d_in[0];  // [4,64,64,64]
    const float* filters = (const float*)d_in[1];  // [64,64,10,10]
    const float* biases  = (const float*)d_in[2];  // [64,1]
    float* out = (float*)d_out;                    // [4,64,64,64]
    (void)in_sizes; (void)n_in; (void)out_size;

    static int attr_set = 0;
    if (!attr_set) {
        cudaFuncSetAttribute(poly_mma,
                             cudaFuncAttributeMaxDynamicSharedMemorySize,
                             SMEM_SZ);
        attr_set = 1;
    }
    poly_prep<<<64, 256>>>(filters, biases);
    poly_mma<<<256, 128, SMEM_SZ>>>(x, out);
}

// round 11
// speedup vs baseline: 1.1929x; 1.0006x over previous
#include <cuda_runtime.h>
#include <cuda_fp16.h>
#include <cstdint>

// ---------------------------------------------------------------------------
// Poly2d via warp-level HMMA (mma.sync m16n8k16, fp16 in / fp32 acc).
// 54 features/channel (9 linear + 45 symmetric pairs); const term folded
// into bias. Round 11: K packed as 2x(54+2) = 112 per channel pair (7
// k-steps, -12.5% HMMA) using plain 240B-stride rows (no swizzle; 15
// super-banks, coprime with 8 -> ldmatrix conflict-free).
// 256 CTAs x 128 threads (2x2 warp grid), 2 CTAs/SM.
// ---------------------------------------------------------------------------

#define NCH   64
#define NOUT  64
#define KPAIR 112                 // halves per channel pair (2 x 56)
#define ROWB  240                 // smem row stride in bytes (112*2 pad to 240)

__device__ __align__(16) unsigned short g_Wp[32 * NOUT * KPAIR];  // [pair][o][112]
__device__ float g_bias2[NOUT];

// dynamic smem layout (bytes)
#define A_BUF  (128 * ROWB)                  // 30720
#define B_BUF  (NOUT * ROWB)                 // 15360
#define OFF_A  0                             // 2 x A_BUF = 61440
#define OFF_B  (2 * A_BUF)                   // 2 x B_BUF = 30720
#define OFF_X  (OFF_B + 2 * B_BUF)           // 2 x 408 floats = 3264
#define SMEM_SZ (OFF_X + 3264 + 64)

__device__ __forceinline__ uint32_t s2u(const void* p) {
    return (uint32_t)__cvta_generic_to_shared(p);
}
__device__ __forceinline__ void cpa4(uint32_t s, const void* g, bool ok) {
    asm volatile("cp.async.ca.shared.global [%0], [%1], 4, %2;\n"
                 :: "r"(s), "l"(g), "r"(ok ? 4 : 0));
}
__device__ __forceinline__ void cpa16(uint32_t s, const void* g) {
    asm volatile("cp.async.cg.shared.global [%0], [%1], 16;\n"
                 :: "r"(s), "l"(g));
}
__device__ __forceinline__ void ldsm4(uint32_t& r0, uint32_t& r1, uint32_t& r2,
                                      uint32_t& r3, uint32_t addr) {
    asm volatile("ldmatrix.sync.aligned.m8n8.x4.shared.b16 {%0,%1,%2,%3}, [%4];"
                 : "=r"(r0), "=r"(r1), "=r"(r2), "=r"(r3) : "r"(addr));
}
__device__ __forceinline__ void mma16816(float& c0, float& c1, float& c2, float& c3,
                                         uint32_t a0, uint32_t a1, uint32_t a2,
                                         uint32_t a3, uint32_t b0, uint32_t b1) {
    asm volatile(
        "mma.sync.aligned.m16n8k16.row.col.f32.f16.f16.f32 "
        "{%0,%1,%2,%3}, {%4,%5,%6,%7}, {%8,%9}, {%0,%1,%2,%3};"
        : "+f"(c0), "+f"(c1), "+f"(c2), "+f"(c3)
        : "r"(a0), "r"(a1), "r"(a2), "r"(a3), "r"(b0), "r"(b1));
}

// ---------------------------------------------------------------------------
// Prep: pack symmetric weights for channel pair -> fp16 [o][2x56] blocks.
// block = pair (32 blocks), 256 threads; filters staged coalesced per channel.
// ---------------------------------------------------------------------------
__global__ void __launch_bounds__(256)
poly_prep(const float* __restrict__ filters, const float* __restrict__ biases) {
    __shared__ float fsm[NOUT * 100];                        // 25.6KB
    __shared__ __align__(16) unsigned short wsm[NOUT * KPAIR];  // 14.3KB
    const int pj = blockIdx.x, tid = threadIdx.x;

    #pragma unroll 1
    for (int p = 0; p < 2; ++p) {
        const int c = 2 * pj + p;
        for (int i = tid; i < NOUT * 100; i += 256)
            fsm[i] = filters[(i / 100) * 6400 + c * 100 + (i % 100)];
        __syncthreads();

        if (tid < NOUT) {
            const int o = tid;
            const float* F = fsm + o * 100;
            float v[56];
            int k = 0;
            #pragma unroll
            for (int t = 1; t <= 9; ++t) v[k++] = F[t] + F[t * 10];
            #pragma unroll
            for (int i = 1; i <= 9; ++i)
                #pragma unroll
                for (int j = i; j <= 9; ++j)
                    v[k++] = (i == j) ? F[i * 10 + i]
                                      : (F[i * 10 + j] + F[j * 10 + i]);
            v[54] = 0.0f; v[55] = 0.0f;
            #pragma unroll
            for (int kk = 0; kk < 56; ++kk)
                wsm[o * KPAIR + p * 56 + kk] =
                    __half_as_ushort(__float2half_rn(v[kk]));
        }
        __syncthreads();   // wsm writes done; fsm reusable next p
    }

    uint4* dst = (uint4*)(g_Wp + pj * NOUT * KPAIR);
    const uint4* srcp = (const uint4*)wsm;
    for (int i = tid; i < 896; i += 256) dst[i] = srcp[i];

    if (pj == 0 && tid < NOUT) {
        float s = biases[tid];
        for (int cc = 0; cc < NCH; ++cc) s += filters[tid * 6400 + cc * 100];
        g_bias2[tid] = s;
    }
}

// ---------------------------------------------------------------------------
// Main kernel: 256 CTAs (b, row) x 128 threads (4 warps), 2x2 warp grid over
// D[64 px, 64 o]; iter = channel pair, K = 112 (7 k-steps). 2 CTAs/SM.
// Featgen: thread = pixel (tid&63) x channel-of-pair (tid>>6).
// ---------------------------------------------------------------------------
extern __shared__ unsigned char smdyn[];

__global__ void __launch_bounds__(128, 2)
poly_mma(const float* __restrict__ x, float* __restrict__ out) {
    const uint32_t smb = s2u(smdyn);
    const int tid = threadIdx.x, lane = tid & 31, wid = tid >> 5;
    const int m = tid & 63, h = tid >> 6;           // pixel col, pair-channel
    const int mrow = wid >> 1, ncol = wid & 1;      // 2x2 warp grid
    const int b = blockIdx.x >> 6;
    const int r = blockIdx.x & 63;

    float acc[2][4][4];
    #pragma unroll
    for (int mt = 0; mt < 2; ++mt)
        #pragma unroll
        for (int n8 = 0; n8 < 4; ++n8)
            #pragma unroll
            for (int q = 0; q < 4; ++q) acc[mt][n8][q] = 0.0f;

    // stage channel pair j into buffer j&1
    auto stage = [&](int j) {
        const uint32_t buf = (uint32_t)(j & 1);
        #pragma unroll
        for (int i = tid; i < 408; i += 128) {      // 2 ch x 3 rows x 68 cols
            const int p = i / 204, rem = i % 204;
            const int rr = rem / 68, col = rem % 68;
            const int gr = r - 1 + rr, gw = col - 1;
            const bool ok = ((unsigned)gr < 64u) && ((unsigned)gw < 64u);
            const int c = 2 * j + p;
            const float* src =
                x + (((b * NCH + c) * 64 + (ok ? gr : 0)) * 64 + (ok ? gw : 0));
            cpa4(smb + OFF_X + (buf * 408 + (uint32_t)i) * 4, src, ok);
        }
        // weights: 64 rows x 14 chunks of 16B -> 240B-stride rows
        const uint4* srcw = (const uint4*)(g_Wp + j * NOUT * KPAIR);
        #pragma unroll
        for (int i = tid; i < 896; i += 128) {
            const int row = i / 14, col = i % 14;
            cpa16(smb + OFF_B + buf * B_BUF + (uint32_t)(row * ROWB + col * 16),
                  srcw + i);
        }
    };

    stage(0);
    asm volatile("cp.async.commit_group;" ::: "memory");

    // ldmatrix lane base offsets (no swizzle; k-step adds ks*32 bytes)
    uint32_t a_off[2], b_off[2];
    #pragma unroll
    for (int mt = 0; mt < 2; ++mt)
        a_off[mt] = (uint32_t)((mrow * 32 + mt * 16 + (lane & 15)) * ROWB +
                               (lane >> 4) * 16);
    #pragma unroll
    for (int nt = 0; nt < 2; ++nt)
        b_off[nt] = (uint32_t)((ncol * 32 + nt * 16 + (lane & 15)) * ROWB +
                               (lane >> 4) * 16);

    for (int j = 0; j < NCH / 2; ++j) {
        asm volatile("cp.async.wait_group 0;" ::: "memory");
        __syncthreads();   // x[j], B[j] ready; A[j&1] free (MMA j-2 done)

        if (j + 1 < NCH / 2) stage(j + 1);
        asm volatile("cp.async.commit_group;" ::: "memory");

        const uint32_t abuf = smb + OFF_A + (uint32_t)(j & 1) * A_BUF;
        const uint32_t bbuf = smb + OFF_B + (uint32_t)(j & 1) * B_BUF;

        // ---- featgen: this thread's channel (h) of the pair ----
        {
            const float* xbp =
                (const float*)(smdyn + OFF_X) + (j & 1) * 408 + h * 204;
            float t[9];
            #pragma unroll
            for (int rr = 0; rr < 3; ++rr)
                #pragma unroll
                for (int dx = 0; dx < 3; ++dx)
                    t[rr * 3 + dx] = xbp[rr * 68 + m + dx];

            float fl[54];
            #pragma unroll
            for (int tt = 0; tt < 9; ++tt) fl[tt] = t[tt];
            {
                int k = 9;
                #pragma unroll
                for (int i = 0; i < 9; ++i)
                    #pragma unroll
                    for (int jj = i; jj < 9; ++jj) fl[k++] = t[i] * t[jj];
            }

            uint32_t hr[28];
            #pragma unroll
            for (int u = 0; u < 27; ++u) {
                __half2 hh = __floats2half2_rn(fl[2 * u], fl[2 * u + 1]);
                hr[u] = *reinterpret_cast<uint32_t*>(&hh);
            }
            hr[27] = 0u;   // pad halves 54,55

            const uint32_t dst0 = abuf + (uint32_t)(m * ROWB + h * 112);
            #pragma unroll
            for (int q = 0; q < 7; ++q)
                asm volatile("st.shared.v4.b32 [%0], {%1,%2,%3,%4};"
                             :: "r"(dst0 + (uint32_t)q * 16),
                                "r"(hr[4 * q]), "r"(hr[4 * q + 1]),
                                "r"(hr[4 * q + 2]), "r"(hr[4 * q + 3])
                             : "memory");
        }
        __syncthreads();   // A pair ready

        // ---- HMMA over K = 112 (7 k-steps) ----
        #pragma unroll
        for (int ks = 0; ks < 7; ++ks) {
            const uint32_t kl = (uint32_t)ks * 32;
            uint32_t a0[4], a1[4], bA[4], bB[4];
            ldsm4(a0[0], a0[1], a0[2], a0[3], abuf + a_off[0] + kl);
            ldsm4(a1[0], a1[1], a1[2], a1[3], abuf + a_off[1] + kl);
            ldsm4(bA[0], bA[1], bA[2], bA[3], bbuf + b_off[0] + kl);
            ldsm4(bB[0], bB[1], bB[2], bB[3], bbuf + b_off[1] + kl);

            mma16816(acc[0][0][0], acc[0][0][1], acc[0][0][2], acc[0][0][3],
                     a0[0], a0[1], a0[2], a0[3], bA[0], bA[2]);
            mma16816(acc[0][1][0], acc[0][1][1], acc[0][1][2], acc[0][1][3],
                     a0[0], a0[1], a0[2], a0[3], bA[1], bA[3]);
            mma16816(acc[0][2][0], acc[0][2][1], acc[0][2][2], acc[0][2][3],
                     a0[0], a0[1], a0[2], a0[3], bB[0], bB[2]);
            mma16816(acc[0][3][0], acc[0][3][1], acc[0][3][2], acc[0][3][3],
                     a0[0], a0[1], a0[2], a0[3], bB[1], bB[3]);
            mma16816(acc[1][0][0], acc[1][0][1], acc[1][0][2], acc[1][0][3],
                     a1[0], a1[1], a1[2], a1[3], bA[0], bA[2]);
            mma16816(acc[1][1][0], acc[1][1][1], acc[1][1][2], acc[1][1][3],
                     a1[0], a1[1], a1[2], a1[3], bA[1], bA[3]);
            mma16816(acc[1][2][0], acc[1][2][1], acc[1][2][2], acc[1][2][3],
                     a1[0], a1[1], a1[2], a1[3], bB[0], bB[2]);
            mma16816(acc[1][3][0], acc[1][3][1], acc[1][3][2], acc[1][3][3],
                     a1[0], a1[1], a1[2], a1[3], bB[1], bB[3]);
        }
    }

    // ---- epilogue: c-frag -> global, + bias ----
    const int obase = ncol * 32 + (lane & 3) * 2;
    float2 bias2v[4];
    #pragma unroll
    for (int n8 = 0; n8 < 4; ++n8)
        bias2v[n8] = *(const float2*)(g_bias2 + obase + n8 * 8);

    #pragma unroll
    for (int mt = 0; mt < 2; ++mt) {
        #pragma unroll
        for (int half = 0; half < 2; ++half) {
            const int cc = mrow * 32 + mt * 16 + (lane >> 2) + half * 8;
            float* op = out + ((b * NOUT) * 64 + r) * 64 + cc;
            #pragma unroll
            for (int n8 = 0; n8 < 4; ++n8) {
                const int o = obase + n8 * 8;
                op[(o)     * 4096] = acc[mt][n8][half * 2]     + bias2v[n8].x;
                op[(o + 1) * 4096] = acc[mt][n8][half * 2 + 1] + bias2v[n8].y;
            }
        }
    }
}

// ---------------------------------------------------------------------------
extern "C" void kernel_launch(void* const* d_in, const int* in_sizes, int n_in,
                              void* d_out, int out_size) {
    const float* x       = (const float*)d_in[0];  // [4,64,64,64]
    const float* filters = (const float*)d_in[1];  // [64,64,10,10]
    const float* biases  = (const float*)d_in[2];  // [64,1]
    float* out = (float*)d_out;                    // [4,64,64,64]
    (void)in_sizes; (void)n_in; (void)out_size;

    static int attr_set = 0;
    if (!attr_set) {
        cudaFuncSetAttribute(poly_mma,
                             cudaFuncAttributeMaxDynamicSharedMemorySize,
                             SMEM_SZ);
        attr_set = 1;
    }
    poly_prep<<<32, 256>>>(filters, biases);
    poly_mma<<<256, 128, SMEM_SZ>>>(x, out);
}